// round 6
// baseline (speedup 1.0000x reference)
#include <cuda_runtime.h>
#include <cmath>
#include <cstdint>

#define N_NODES 20000
#define N_EDGES 320000
#define CDIM    128
#define HEADS   8

// ---------------- scratch (device globals; no allocation allowed) ----------------
__device__ __align__(16) float g_sln[N_NODES * CDIM];
__device__ __align__(16) float g_q  [N_NODES * CDIM];
__device__ __align__(16) float g_k  [N_NODES * CDIM];
__device__ __align__(16) float g_h1 [N_NODES * CDIM];
__device__ __align__(16) float g_h2 [N_NODES * CDIM];
__device__ __align__(16) float g_x3 [N_NODES * 3 * CDIM];
__device__ __align__(16) float g_val[N_NODES * 3 * CDIM];
__device__ __align__(16) float g_rattn[(size_t)N_EDGES * CDIM];
__device__ __align__(16) float g_rproj[(size_t)N_EDGES * 3 * CDIM];
__device__ __align__(16) float g_alpha[N_EDGES * HEADS];
__device__ unsigned g_m[N_NODES * HEADS];
__device__ float    g_z[N_NODES * HEADS];

__device__ __forceinline__ unsigned enc_f(float x) {
    unsigned u = __float_as_uint(x);
    return (u & 0x80000000u) ? ~u : (u | 0x80000000u);
}
__device__ __forceinline__ float dec_f(unsigned u) {
    u = (u & 0x80000000u) ? (u & 0x7fffffffu) : ~u;
    return __uint_as_float(u);
}

__device__ __forceinline__ uint32_t tf32u(float x) {
    uint32_t u;
    asm("cvt.rna.tf32.f32 %0, %1;" : "=r"(u) : "f"(x));
    return u;
}

__device__ __forceinline__ void mma_tf32(float* c, const uint32_t* a, const uint32_t* b) {
    asm volatile(
        "mma.sync.aligned.m16n8k8.row.col.f32.tf32.tf32.f32 "
        "{%0,%1,%2,%3}, {%4,%5,%6,%7}, {%8,%9}, {%0,%1,%2,%3};"
        : "+f"(c[0]), "+f"(c[1]), "+f"(c[2]), "+f"(c[3])
        : "r"(a[0]), "r"(a[1]), "r"(a[2]), "r"(a[3]), "r"(b[0]), "r"(b[1]));
}

__device__ __forceinline__ void cp16(uint32_t saddr, const void* gptr, int srcsize) {
    asm volatile("cp.async.cg.shared.global [%0], [%1], 16, %2;"
                 :: "r"(saddr), "l"(gptr), "r"(srcsize));
}
__device__ __forceinline__ void cp_commit() {
    asm volatile("cp.async.commit_group;");
}
__device__ __forceinline__ void cp_wait1() {
    asm volatile("cp.async.wait_group 1;");
}
__device__ __forceinline__ void cp_wait0() {
    asm volatile("cp.async.wait_group 0;");
}

__device__ __forceinline__ void red4(float* p, float4 v) {
    asm volatile("red.global.add.v4.f32 [%0], {%1, %2, %3, %4};"
                 :: "l"(p), "f"(v.x), "f"(v.y), "f"(v.z), "f"(v.w) : "memory");
}

// ---------------- init accumulators ----------------
__global__ void init_kernel() {
    int i = blockIdx.x * blockDim.x + threadIdx.x;
    if (i < N_NODES * HEADS) {
        g_m[i] = 0x007FFFFFu;  // enc(-inf)
        g_z[i] = 0.0f;
    }
}

// ---------------- layernorm ----------------
__global__ void ln_kernel(const float* __restrict__ s, const float* __restrict__ g,
                          const float* __restrict__ b, float* __restrict__ out_s) {
    int n = blockIdx.x;
    int c = threadIdx.x;
    float x = s[n * CDIM + c];
    __shared__ float red[4];
    int lane = c & 31, w = c >> 5;
    float sum = x;
    #pragma unroll
    for (int o = 16; o > 0; o >>= 1) sum += __shfl_xor_sync(0xffffffffu, sum, o);
    if (lane == 0) red[w] = sum;
    __syncthreads();
    float mean = (red[0] + red[1] + red[2] + red[3]) * (1.0f / 128.0f);
    float d = x - mean;
    float sq = d * d;
    #pragma unroll
    for (int o = 16; o > 0; o >>= 1) sq += __shfl_xor_sync(0xffffffffu, sq, o);
    __syncthreads();
    if (lane == 0) red[w] = sq;
    __syncthreads();
    float var = (red[0] + red[1] + red[2] + red[3]) * (1.0f / 128.0f);
    float y = d * rsqrtf(var + 1e-5f) * g[c] + b[c];
    g_sln[n * CDIM + c] = y;
    out_s[n * CDIM + c] = y;
}

// ============== cp.async 3-stage pipelined tf32 GEMM, K-chunk 32 ==============
// Block tile 128x128, K=128 in 4 chunks of 32, 8 warps, warp tile 32x64.

struct Task {
    const float* A; const float* Bw; const float* bias; float* C;
    int M; int Nc; int act; int bn;
};
struct Task8 { Task t[8]; };

#define A_STRIDE 36
#define B_STRIDE 136
#define A_STAGE  (128 * A_STRIDE)          // 4608 floats
#define B_STAGE  (32 * B_STRIDE)           // 4352 floats
#define B_BASE   (3 * A_STAGE)             // 13824 floats
#define SMEM_BYTES ((B_BASE + 3 * B_STAGE) * 4)  // 107520 bytes

__global__ void __launch_bounds__(256, 2)
gemm_pipe(Task8 ts) {
    extern __shared__ float sm[];
    const Task tk = ts.t[blockIdx.y];
    const int bm = blockIdx.x * 128;
    const int bn = tk.bn;
    const int M = tk.M, Nc = tk.Nc;
    const float* __restrict__ A = tk.A;
    const float* __restrict__ B = tk.Bw;

    const int tid = threadIdx.x;
    const int warp = tid >> 5, lane = tid & 31;
    const int gid = lane >> 2, tig = lane & 3;
    const int wm = (warp & 3) * 32;
    const int wn = (warp >> 2) * 64;

    const uint32_t smbase = (uint32_t)__cvta_generic_to_shared(sm);

    float acc[2][8][4];
    #pragma unroll
    for (int mi = 0; mi < 2; mi++)
        #pragma unroll
        for (int ni = 0; ni < 8; ni++)
            #pragma unroll
            for (int t = 0; t < 4; t++) acc[mi][ni][t] = 0.0f;

    // copy one 32-K chunk into stage slot st
    auto issue = [&](int st, int k0) {
        #pragma unroll
        for (int r = 0; r < 4; r++) {
            int idx = tid + r * 256;            // 0..1023
            int row = idx >> 3;                 // 0..127
            int kq  = (idx & 7) << 2;           // 0..28
            int gr = bm + row;
            const float* ga = A + (size_t)(gr < M ? gr : M - 1) * 128 + k0 + kq;
            cp16(smbase + (st * A_STAGE + row * A_STRIDE + kq) * 4, ga, gr < M ? 16 : 0);
        }
        #pragma unroll
        for (int r = 0; r < 4; r++) {
            int idx = tid + r * 256;
            int kr = idx >> 5;                  // 0..31
            int nq = (idx & 31) << 2;           // 0..124
            cp16(smbase + (B_BASE + st * B_STAGE + kr * B_STRIDE + nq) * 4,
                 B + (size_t)(k0 + kr) * Nc + bn + nq, 16);
        }
    };

    issue(0, 0);  cp_commit();
    issue(1, 32); cp_commit();

    #pragma unroll
    for (int c = 0; c < 4; c++) {
        if (c < 3) cp_wait1(); else cp_wait0();
        __syncthreads();
        if (c < 2) { issue((c + 2) % 3, (c + 2) * 32); cp_commit(); }

        const float* As = sm + (c % 3) * A_STAGE;
        const float* Bs = sm + B_BASE + (c % 3) * B_STAGE;
        #pragma unroll
        for (int kk = 0; kk < 32; kk += 8) {
            uint32_t bf[8][2];
            #pragma unroll
            for (int ni = 0; ni < 8; ni++) {
                bf[ni][0] = tf32u(Bs[(kk + tig    ) * B_STRIDE + wn + ni * 8 + gid]);
                bf[ni][1] = tf32u(Bs[(kk + tig + 4) * B_STRIDE + wn + ni * 8 + gid]);
            }
            #pragma unroll
            for (int mi = 0; mi < 2; mi++) {
                uint32_t af[4];
                af[0] = tf32u(As[(wm + mi * 16 + gid    ) * A_STRIDE + kk + tig    ]);
                af[1] = tf32u(As[(wm + mi * 16 + gid + 8) * A_STRIDE + kk + tig    ]);
                af[2] = tf32u(As[(wm + mi * 16 + gid    ) * A_STRIDE + kk + tig + 4]);
                af[3] = tf32u(As[(wm + mi * 16 + gid + 8) * A_STRIDE + kk + tig + 4]);
                #pragma unroll
                for (int ni = 0; ni < 8; ni++) mma_tf32(acc[mi][ni], af, bf[ni]);
            }
        }
        __syncthreads();
    }

    #pragma unroll
    for (int mi = 0; mi < 2; mi++) {
        int r0 = bm + wm + mi * 16 + gid;
        int r1 = r0 + 8;
        #pragma unroll
        for (int ni = 0; ni < 8; ni++) {
            int col = bn + wn + ni * 8 + tig * 2;
            float bb0 = tk.bias[col], bb1 = tk.bias[col + 1];
            float v0 = acc[mi][ni][0] + bb0;
            float v1 = acc[mi][ni][1] + bb1;
            float v2 = acc[mi][ni][2] + bb0;
            float v3 = acc[mi][ni][3] + bb1;
            if (tk.act) {
                v0 = v0 / (1.0f + expf(-v0));
                v1 = v1 / (1.0f + expf(-v1));
                v2 = v2 / (1.0f + expf(-v2));
                v3 = v3 / (1.0f + expf(-v3));
            }
            if (r0 < M) { float2 o = make_float2(v0, v1); *(float2*)(tk.C + (size_t)r0 * Nc + col) = o; }
            if (r1 < M) { float2 o = make_float2(v2, v3); *(float2*)(tk.C + (size_t)r1 * Nc + col) = o; }
        }
    }
}

// ---------------- alpha[e,h] = sum_d q[dst]*k[src]*r_attn, + segment max ----------------
__global__ void alpha_kernel(const int* __restrict__ ei) {
    int warp = (blockIdx.x * blockDim.x + threadIdx.x) >> 5;
    if (warp >= N_EDGES) return;
    int lane = threadIdx.x & 31;
    int src = ei[warp];
    int dst = ei[N_EDGES + warp];
    float4 qv = *(const float4*)&g_q[(size_t)dst * CDIM + lane * 4];
    float4 kv = *(const float4*)&g_k[(size_t)src * CDIM + lane * 4];
    float4 rv = *(const float4*)&g_rattn[(size_t)warp * CDIM + lane * 4];
    float p = qv.x * kv.x * rv.x + qv.y * kv.y * rv.y + qv.z * kv.z * rv.z + qv.w * kv.w * rv.w;
    p += __shfl_xor_sync(0xffffffffu, p, 1);
    p += __shfl_xor_sync(0xffffffffu, p, 2);
    if ((lane & 3) == 0) {
        int h = lane >> 2;
        g_alpha[(size_t)warp * HEADS + h] = p;
        atomicMax(&g_m[dst * HEADS + h], enc_f(p));
    }
}

// ---------------- e = exp(alpha - m[dst]); z[dst] += e ----------------
__global__ void exp_kernel(const int* __restrict__ ei) {
    int i = blockIdx.x * blockDim.x + threadIdx.x;
    if (i >= N_EDGES * HEADS) return;
    int e = i >> 3;
    int h = i & 7;
    int dst = ei[N_EDGES + e];
    float m = dec_f(g_m[dst * HEADS + h]);
    if (!isfinite(m)) m = 0.0f;
    float ex = expf(g_alpha[i] - m);
    g_alpha[i] = ex;
    atomicAdd(&g_z[dst * HEADS + h], ex);
}

// ---------------- per-edge message + vectorized scatter-add ----------------
__global__ void msg_kernel(const int* __restrict__ ei, const float* __restrict__ dir,
                           const float* __restrict__ dij, const float* __restrict__ v,
                           float* __restrict__ out_s, float* __restrict__ out_v) {
    __shared__ float ms[384];
    __shared__ float sa[8];
    int e = blockIdx.x;
    int c = threadIdx.x;  // 128
    int src = ei[e];
    int dst = ei[N_EDGES + e];
    float d = dij[e];
    float cc = (d < 5.0f) ? 0.5f * (cosf(d * 0.62831853071795865f) + 1.0f) : 0.0f;

    if (c < 8) sa[c] = g_alpha[(size_t)e * HEADS + c] / (g_z[dst * HEADS + c] + 1e-16f);
    __syncthreads();

    const float* rp  = g_rproj + (size_t)e * 384;
    const float* x3s = g_x3 + (size_t)src * 384;
    const float* vs  = g_val + (size_t)src * 384;

    #pragma unroll
    for (int t = 0; t < 3; t++) {
        int j = c + t * 128;
        int h = j / 48;
        ms[j] = rp[j] * x3s[j] * cc + sa[h] * vs[j];
    }
    __syncthreads();

    if (c < 32) {
        float4 m4 = *(const float4*)&ms[c * 4];
        red4(&out_s[(size_t)dst * 128 + c * 4], m4);
    } else {
        int q = c - 32;
        int seg = q >> 5, t = q & 31;
        float dseg = dir[e * 3 + seg];
        float4 m1 = *(const float4*)&ms[128 + t * 4];
        float4 m2 = *(const float4*)&ms[256 + t * 4];
        float4 vv = *(const float4*)(v + (size_t)src * 384 + seg * 128 + t * 4);
        float4 r;
        r.x = dseg * m1.x + m2.x * vv.x;
        r.y = dseg * m1.y + m2.y * vv.y;
        r.z = dseg * m1.z + m2.z * vv.z;
        r.w = dseg * m1.w + m2.w * vv.w;
        red4(&out_v[(size_t)dst * 384 + seg * 128 + t * 4], r);
    }
}

// ---------------- launch ----------------
extern "C" void kernel_launch(void* const* d_in, const int* in_sizes, int n_in,
                              void* d_out, int out_size) {
    const float* s   = (const float*)d_in[0];
    const float* v   = (const float*)d_in[1];
    const float* dir = (const float*)d_in[2];
    const float* dij = (const float*)d_in[3];
    const float* rij = (const float*)d_in[4];
    const int*   ei  = (const int*)d_in[5];
    const float* lng = (const float*)d_in[6];
    const float* lnb = (const float*)d_in[7];
    const float* Wq  = (const float*)d_in[8];  const float* bq  = (const float*)d_in[9];
    const float* Wk  = (const float*)d_in[10]; const float* bk  = (const float*)d_in[11];
    const float* Wg1 = (const float*)d_in[12]; const float* bg1 = (const float*)d_in[13];
    const float* Wg2 = (const float*)d_in[14]; const float* bg2 = (const float*)d_in[15];
    const float* Wv1 = (const float*)d_in[16]; const float* bv1 = (const float*)d_in[17];
    const float* Wv2 = (const float*)d_in[18]; const float* bv2 = (const float*)d_in[19];
    const float* Wre = (const float*)d_in[20]; const float* bre = (const float*)d_in[21];
    const float* Wra = (const float*)d_in[22]; const float* bra = (const float*)d_in[23];

    float* out   = (float*)d_out;
    float* out_s = out;
    float* out_v = out + (size_t)N_NODES * CDIM;
    float* out_r = out_v + (size_t)N_NODES * 3 * CDIM;

    float *p_sln, *p_q, *p_k, *p_h1, *p_h2, *p_x3, *p_val, *p_rattn, *p_rproj;
    cudaGetSymbolAddress((void**)&p_sln,   g_sln);
    cudaGetSymbolAddress((void**)&p_q,     g_q);
    cudaGetSymbolAddress((void**)&p_k,     g_k);
    cudaGetSymbolAddress((void**)&p_h1,    g_h1);
    cudaGetSymbolAddress((void**)&p_h2,    g_h2);
    cudaGetSymbolAddress((void**)&p_x3,    g_x3);
    cudaGetSymbolAddress((void**)&p_val,   g_val);
    cudaGetSymbolAddress((void**)&p_rattn, g_rattn);
    cudaGetSymbolAddress((void**)&p_rproj, g_rproj);

    cudaFuncSetAttribute(gemm_pipe, cudaFuncAttributeMaxDynamicSharedMemorySize, SMEM_BYTES);

    cudaMemcpyAsync(out_v, v,   sizeof(float) * (size_t)N_NODES * 3 * CDIM,
                    cudaMemcpyDeviceToDevice, 0);
    cudaMemcpyAsync(out_r, rij, sizeof(float) * (size_t)N_EDGES * CDIM,
                    cudaMemcpyDeviceToDevice, 0);

    init_kernel<<<(N_NODES * HEADS + 255) / 256, 256>>>();
    ln_kernel<<<N_NODES, 128>>>(s, lng, lnb, out_s);

    const int mb_n = (N_NODES + 127) / 128;   // 157
    const int mb_e = N_EDGES / 128;           // 2500

    // 4 node GEMMs (C->C), one launch, task = blockIdx.y
    Task8 tA;
    tA.t[0] = { p_sln, Wq,  bq,  p_q,  N_NODES, 128, 0, 0 };
    tA.t[1] = { p_sln, Wk,  bk,  p_k,  N_NODES, 128, 0, 0 };
    tA.t[2] = { p_sln, Wg1, bg1, p_h1, N_NODES, 128, 1, 0 };
    tA.t[3] = { p_sln, Wv1, bv1, p_h2, N_NODES, 128, 1, 0 };
    tA.t[4] = tA.t[0]; tA.t[5] = tA.t[0]; tA.t[6] = tA.t[0]; tA.t[7] = tA.t[0];
    gemm_pipe<<<dim3(mb_n, 4), 256, SMEM_BYTES>>>(tA);

    // 2 node GEMMs (C->3C) x 3 column tiles, one launch
    Task8 tB;
    tB.t[0] = { p_h1, Wg2, bg2, p_x3,  N_NODES, 384, 0, 0   };
    tB.t[1] = { p_h1, Wg2, bg2, p_x3,  N_NODES, 384, 0, 128 };
    tB.t[2] = { p_h1, Wg2, bg2, p_x3,  N_NODES, 384, 0, 256 };
    tB.t[3] = { p_h2, Wv2, bv2, p_val, N_NODES, 384, 0, 0   };
    tB.t[4] = { p_h2, Wv2, bv2, p_val, N_NODES, 384, 0, 128 };
    tB.t[5] = { p_h2, Wv2, bv2, p_val, N_NODES, 384, 0, 256 };
    tB.t[6] = tB.t[0]; tB.t[7] = tB.t[0];
    gemm_pipe<<<dim3(mb_n, 6), 256, SMEM_BYTES>>>(tB);

    // edge GEMMs: Wra (3 column tiles) + Wre (silu), one launch
    Task8 tE;
    tE.t[0] = { rij, Wra, bra, p_rproj, N_EDGES, 384, 0, 0   };
    tE.t[1] = { rij, Wra, bra, p_rproj, N_EDGES, 384, 0, 128 };
    tE.t[2] = { rij, Wra, bra, p_rproj, N_EDGES, 384, 0, 256 };
    tE.t[3] = { rij, Wre, bre, p_rattn, N_EDGES, 128, 1, 0   };
    tE.t[4] = tE.t[0]; tE.t[5] = tE.t[0]; tE.t[6] = tE.t[0]; tE.t[7] = tE.t[0];
    gemm_pipe<<<dim3(mb_e, 4), 256, SMEM_BYTES>>>(tE);

    alpha_kernel<<<N_EDGES / 8, 256>>>(ei);
    exp_kernel<<<(N_EDGES * HEADS + 255) / 256, 256>>>(ei);
    msg_kernel<<<N_EDGES, 128>>>(ei, dir, dij, v, out_s, out_v);
}

// round 8
// speedup vs baseline: 1.0734x; 1.0734x over previous
#include <cuda_runtime.h>
#include <cmath>
#include <cstdint>

#define N_NODES 20000
#define N_EDGES 320000
#define CDIM    128
#define HEADS   8

// ---------------- scratch (device globals; no allocation allowed) ----------------
__device__ __align__(16) float g_sln[N_NODES * CDIM];       // tf32-rounded
__device__ __align__(16) float g_q  [N_NODES * CDIM];
__device__ __align__(16) float g_k  [N_NODES * CDIM];
__device__ __align__(16) float g_h1 [N_NODES * CDIM];       // tf32-rounded
__device__ __align__(16) float g_h2 [N_NODES * CDIM];       // tf32-rounded
__device__ __align__(16) float g_x3 [N_NODES * 3 * CDIM];
__device__ __align__(16) float g_val[N_NODES * 3 * CDIM];
__device__ __align__(16) float g_rattn[(size_t)N_EDGES * CDIM];
__device__ __align__(16) float g_rproj[(size_t)N_EDGES * 3 * CDIM];
__device__ __align__(16) float g_rijc[(size_t)N_EDGES * CDIM];  // tf32-rounded rij
__device__ __align__(16) float g_wc[229376];                 // tf32-rounded weights
__device__ __align__(16) float g_alpha[N_EDGES * HEADS];
__device__ unsigned g_m[N_NODES * HEADS];
__device__ float    g_z[N_NODES * HEADS];

// weight offsets inside g_wc
#define WQ_OFF  0
#define WK_OFF  16384
#define WG1_OFF 32768
#define WV1_OFF 49152
#define WG2_OFF 65536
#define WV2_OFF 114688
#define WRE_OFF 163840
#define WRA_OFF 180224

__device__ __forceinline__ unsigned enc_f(float x) {
    unsigned u = __float_as_uint(x);
    return (u & 0x80000000u) ? ~u : (u | 0x80000000u);
}
__device__ __forceinline__ float dec_f(unsigned u) {
    u = (u & 0x80000000u) ? (u & 0x7fffffffu) : ~u;
    return __uint_as_float(u);
}

__device__ __forceinline__ float tf32r(float x) {
    uint32_t u;
    asm("cvt.rna.tf32.f32 %0, %1;" : "=r"(u) : "f"(x));
    return __uint_as_float(u);
}

__device__ __forceinline__ void mma_tf32(float* c, const uint32_t* a, const uint32_t* b) {
    asm volatile(
        "mma.sync.aligned.m16n8k8.row.col.f32.tf32.tf32.f32 "
        "{%0,%1,%2,%3}, {%4,%5,%6,%7}, {%8,%9}, {%0,%1,%2,%3};"
        : "+f"(c[0]), "+f"(c[1]), "+f"(c[2]), "+f"(c[3])
        : "r"(a[0]), "r"(a[1]), "r"(a[2]), "r"(a[3]), "r"(b[0]), "r"(b[1]));
}

__device__ __forceinline__ void cp16(uint32_t saddr, const void* gptr, int srcsize) {
    asm volatile("cp.async.cg.shared.global [%0], [%1], 16, %2;"
                 :: "r"(saddr), "l"(gptr), "r"(srcsize));
}
__device__ __forceinline__ void cp_commit() { asm volatile("cp.async.commit_group;"); }
__device__ __forceinline__ void cp_wait2()  { asm volatile("cp.async.wait_group 2;"); }

__device__ __forceinline__ void red4(float* p, float4 v) {
    asm volatile("red.global.add.v4.f32 [%0], {%1, %2, %3, %4};"
                 :: "l"(p), "f"(v.x), "f"(v.y), "f"(v.z), "f"(v.w) : "memory");
}

// ---------------- init accumulators ----------------
__global__ void init_kernel() {
    int i = blockIdx.x * blockDim.x + threadIdx.x;
    if (i < N_NODES * HEADS) {
        g_m[i] = 0x007FFFFFu;  // enc(-inf)
        g_z[i] = 0.0f;
    }
}

// ---------------- weight pre-conversion to tf32 ----------------
struct WSrc { const float* p[8]; };
__global__ void conv_w_kernel(WSrc ws) {
    const int sizes[8] = {16384, 16384, 16384, 16384, 49152, 49152, 16384, 49152};
    const int offs[8]  = {WQ_OFF, WK_OFF, WG1_OFF, WV1_OFF, WG2_OFF, WV2_OFF, WRE_OFF, WRA_OFF};
    int r = blockIdx.y;
    int i = blockIdx.x * blockDim.x + threadIdx.x;
    if (i < sizes[r]) g_wc[offs[r] + i] = tf32r(ws.p[r][i]);
}

// ---------------- rij: copy to out_r + tf32-rounded copy for GEMM A ----------------
__global__ void conv_rij_kernel(const float* __restrict__ rij, float* __restrict__ out_r) {
    size_t i = (size_t)(blockIdx.x * blockDim.x + threadIdx.x) * 4;
    if (i >= (size_t)N_EDGES * CDIM) return;
    float4 v4 = *(const float4*)(rij + i);
    *(float4*)(out_r + i) = v4;
    v4.x = tf32r(v4.x); v4.y = tf32r(v4.y); v4.z = tf32r(v4.z); v4.w = tf32r(v4.w);
    *(float4*)(g_rijc + i) = v4;
}

// ---------------- layernorm ----------------
__global__ void ln_kernel(const float* __restrict__ s, const float* __restrict__ g,
                          const float* __restrict__ b, float* __restrict__ out_s) {
    int n = blockIdx.x;
    int c = threadIdx.x;
    float x = s[n * CDIM + c];
    __shared__ float red[4];
    int lane = c & 31, w = c >> 5;
    float sum = x;
    #pragma unroll
    for (int o = 16; o > 0; o >>= 1) sum += __shfl_xor_sync(0xffffffffu, sum, o);
    if (lane == 0) red[w] = sum;
    __syncthreads();
    float mean = (red[0] + red[1] + red[2] + red[3]) * (1.0f / 128.0f);
    float d = x - mean;
    float sq = d * d;
    #pragma unroll
    for (int o = 16; o > 0; o >>= 1) sq += __shfl_xor_sync(0xffffffffu, sq, o);
    __syncthreads();
    if (lane == 0) red[w] = sq;
    __syncthreads();
    float var = (red[0] + red[1] + red[2] + red[3]) * (1.0f / 128.0f);
    float y = d * rsqrtf(var + 1e-5f) * g[c] + b[c];
    g_sln[n * CDIM + c] = tf32r(y);  // GEMM-A copy, pre-rounded
    out_s[n * CDIM + c] = y;
}

// ============== cp.async 4-stage pipelined tf32 GEMM, K-chunk 16 ==============
// Operands pre-rounded to tf32 in gmem -> no cvt in the mainloop.
// Block tile 128x128, 8 warps, warp tile 32x64. 1-D grid, task by block offset.

struct Task {
    const float* A; const float* Bw; const float* bias; float* C;
    int M; int Nc; int act; int bn; int rnd; int blk0;
};
struct Task8 { Task t[8]; };

#define A_STRIDE 20
#define B_STRIDE 136
#define A_STAGE  (128 * A_STRIDE)
#define B_STAGE  (16 * B_STRIDE)
#define B_BASE   (4 * A_STAGE)
#define SMEM_BYTES ((B_BASE + 4 * B_STAGE) * 4)  // 75776 bytes

__global__ void __launch_bounds__(256)
gemm_pipe(Task8 ts) {
    extern __shared__ float sm[];
    int ti = 0;
    #pragma unroll
    for (int i = 1; i < 8; i++)
        if ((int)blockIdx.x >= ts.t[i].blk0) ti = i;
    const Task tk = ts.t[ti];
    const int bm = (blockIdx.x - tk.blk0) * 128;
    const int bn = tk.bn;
    const int M = tk.M, Nc = tk.Nc;
    const float* __restrict__ A = tk.A;
    const float* __restrict__ B = tk.Bw;

    const int tid = threadIdx.x;
    const int warp = tid >> 5, lane = tid & 31;
    const int gid = lane >> 2, tig = lane & 3;
    const int wm = (warp & 3) * 32;
    const int wn = (warp >> 2) * 64;

    const int arow = tid >> 2, akq = (tid & 3) << 2;
    const int bkr = tid >> 5, bnq = (tid & 31) << 2;
    const uint32_t smbase = (uint32_t)__cvta_generic_to_shared(sm);

    float acc[2][8][4];
    #pragma unroll
    for (int mi = 0; mi < 2; mi++)
        #pragma unroll
        for (int ni = 0; ni < 8; ni++)
            #pragma unroll
            for (int t = 0; t < 4; t++) acc[mi][ni][t] = 0.0f;

    auto issue = [&](int st, int k0) {
        int r0 = bm + arow, r1 = r0 + 64;
        const float* ga0 = A + (size_t)(r0 < M ? r0 : M - 1) * 128 + k0 + akq;
        const float* ga1 = A + (size_t)(r1 < M ? r1 : M - 1) * 128 + k0 + akq;
        cp16(smbase + (st * A_STAGE + arow * A_STRIDE + akq) * 4,        ga0, r0 < M ? 16 : 0);
        cp16(smbase + (st * A_STAGE + (arow + 64) * A_STRIDE + akq) * 4, ga1, r1 < M ? 16 : 0);
        const float* gb0 = B + (size_t)(k0 + bkr) * Nc + bn + bnq;
        const float* gb1 = B + (size_t)(k0 + bkr + 8) * Nc + bn + bnq;
        cp16(smbase + (B_BASE + st * B_STAGE + bkr * B_STRIDE + bnq) * 4,       gb0, 16);
        cp16(smbase + (B_BASE + st * B_STAGE + (bkr + 8) * B_STRIDE + bnq) * 4, gb1, 16);
    };

    issue(0, 0);  cp_commit();
    issue(1, 16); cp_commit();
    issue(2, 32); cp_commit();

    #pragma unroll
    for (int c = 0; c < 8; c++) {
        const int buf = c & 3;
        cp_wait2();
        __syncthreads();
        if (c < 5) issue((c + 3) & 3, (c + 3) * 16);
        cp_commit();

        const uint32_t* As = (const uint32_t*)(sm + buf * A_STAGE);
        const uint32_t* Bs = (const uint32_t*)(sm + B_BASE + buf * B_STAGE);
        #pragma unroll
        for (int kk = 0; kk < 16; kk += 8) {
            uint32_t bf[8][2];
            #pragma unroll
            for (int ni = 0; ni < 8; ni++) {
                bf[ni][0] = Bs[(kk + tig    ) * B_STRIDE + wn + ni * 8 + gid];
                bf[ni][1] = Bs[(kk + tig + 4) * B_STRIDE + wn + ni * 8 + gid];
            }
            #pragma unroll
            for (int mi = 0; mi < 2; mi++) {
                uint32_t af[4];
                af[0] = As[(wm + mi * 16 + gid    ) * A_STRIDE + kk + tig    ];
                af[1] = As[(wm + mi * 16 + gid + 8) * A_STRIDE + kk + tig    ];
                af[2] = As[(wm + mi * 16 + gid    ) * A_STRIDE + kk + tig + 4];
                af[3] = As[(wm + mi * 16 + gid + 8) * A_STRIDE + kk + tig + 4];
                #pragma unroll
                for (int ni = 0; ni < 8; ni++) mma_tf32(acc[mi][ni], af, bf[ni]);
            }
        }
        __syncthreads();
    }

    #pragma unroll
    for (int mi = 0; mi < 2; mi++) {
        int r0 = bm + wm + mi * 16 + gid;
        int r1 = r0 + 8;
        #pragma unroll
        for (int ni = 0; ni < 8; ni++) {
            int col = bn + wn + ni * 8 + tig * 2;
            float bb0 = tk.bias[col], bb1 = tk.bias[col + 1];
            float v0 = acc[mi][ni][0] + bb0;
            float v1 = acc[mi][ni][1] + bb1;
            float v2 = acc[mi][ni][2] + bb0;
            float v3 = acc[mi][ni][3] + bb1;
            if (tk.act) {
                v0 = v0 / (1.0f + expf(-v0));
                v1 = v1 / (1.0f + expf(-v1));
                v2 = v2 / (1.0f + expf(-v2));
                v3 = v3 / (1.0f + expf(-v3));
            }
            if (tk.rnd) {  // output feeds a later GEMM as A: pre-round (numerics identical)
                v0 = tf32r(v0); v1 = tf32r(v1); v2 = tf32r(v2); v3 = tf32r(v3);
            }
            if (r0 < M) { float2 o = make_float2(v0, v1); *(float2*)(tk.C + (size_t)r0 * Nc + col) = o; }
            if (r1 < M) { float2 o = make_float2(v2, v3); *(float2*)(tk.C + (size_t)r1 * Nc + col) = o; }
        }
    }
}

// ---------------- alpha[e,h] = sum_d q[dst]*k[src]*r_attn, + segment max ----------------
__global__ void alpha_kernel(const int* __restrict__ ei) {
    int warp = (blockIdx.x * blockDim.x + threadIdx.x) >> 5;
    if (warp >= N_EDGES) return;
    int lane = threadIdx.x & 31;
    int src = ei[warp];
    int dst = ei[N_EDGES + warp];
    float4 qv = *(const float4*)&g_q[(size_t)dst * CDIM + lane * 4];
    float4 kv = *(const float4*)&g_k[(size_t)src * CDIM + lane * 4];
    float4 rv = *(const float4*)&g_rattn[(size_t)warp * CDIM + lane * 4];
    float p = qv.x * kv.x * rv.x + qv.y * kv.y * rv.y + qv.z * kv.z * rv.z + qv.w * kv.w * rv.w;
    p += __shfl_xor_sync(0xffffffffu, p, 1);
    p += __shfl_xor_sync(0xffffffffu, p, 2);
    if ((lane & 3) == 0) {
        int h = lane >> 2;
        g_alpha[(size_t)warp * HEADS + h] = p;
        atomicMax(&g_m[dst * HEADS + h], enc_f(p));
    }
}

// ---------------- e = exp(alpha - m[dst]); z[dst] += e ----------------
__global__ void exp_kernel(const int* __restrict__ ei) {
    int i = blockIdx.x * blockDim.x + threadIdx.x;
    if (i >= N_EDGES * HEADS) return;
    int e = i >> 3;
    int h = i & 7;
    int dst = ei[N_EDGES + e];
    float m = dec_f(g_m[dst * HEADS + h]);
    if (!isfinite(m)) m = 0.0f;
    float ex = expf(g_alpha[i] - m);
    g_alpha[i] = ex;
    atomicAdd(&g_z[dst * HEADS + h], ex);
}

// ---------------- per-edge message + vectorized scatter-add ----------------
__global__ void msg_kernel(const int* __restrict__ ei, const float* __restrict__ dir,
                           const float* __restrict__ dij, const float* __restrict__ v,
                           float* __restrict__ out_s, float* __restrict__ out_v) {
    __shared__ float ms[384];
    __shared__ float sa[8];
    int e = blockIdx.x;
    int c = threadIdx.x;
    int src = ei[e];
    int dst = ei[N_EDGES + e];
    float d = dij[e];
    float cc = (d < 5.0f) ? 0.5f * (cosf(d * 0.62831853071795865f) + 1.0f) : 0.0f;

    if (c < 8) sa[c] = g_alpha[(size_t)e * HEADS + c] / (g_z[dst * HEADS + c] + 1e-16f);
    __syncthreads();

    const float* rp  = g_rproj + (size_t)e * 384;
    const float* x3s = g_x3 + (size_t)src * 384;
    const float* vs  = g_val + (size_t)src * 384;

    #pragma unroll
    for (int t = 0; t < 3; t++) {
        int j = c + t * 128;
        int h = j / 48;
        ms[j] = rp[j] * x3s[j] * cc + sa[h] * vs[j];
    }
    __syncthreads();

    if (c < 32) {
        float4 m4 = *(const float4*)&ms[c * 4];
        red4(&out_s[(size_t)dst * 128 + c * 4], m4);
    } else {
        int q = c - 32;
        int seg = q >> 5, t = q & 31;
        float dseg = dir[e * 3 + seg];
        float4 m1 = *(const float4*)&ms[128 + t * 4];
        float4 m2 = *(const float4*)&ms[256 + t * 4];
        float4 vv = *(const float4*)(v + (size_t)src * 384 + seg * 128 + t * 4);
        float4 r;
        r.x = dseg * m1.x + m2.x * vv.x;
        r.y = dseg * m1.y + m2.y * vv.y;
        r.z = dseg * m1.z + m2.z * vv.z;
        r.w = dseg * m1.w + m2.w * vv.w;
        red4(&out_v[(size_t)dst * 384 + seg * 128 + t * 4], r);
    }
}

// ---------------- launch ----------------
extern "C" void kernel_launch(void* const* d_in, const int* in_sizes, int n_in,
                              void* d_out, int out_size) {
    const float* s   = (const float*)d_in[0];
    const float* v   = (const float*)d_in[1];
    const float* dir = (const float*)d_in[2];
    const float* dij = (const float*)d_in[3];
    const float* rij = (const float*)d_in[4];
    const int*   ei  = (const int*)d_in[5];
    const float* lng = (const float*)d_in[6];
    const float* lnb = (const float*)d_in[7];
    const float* Wq  = (const float*)d_in[8];  const float* bq  = (const float*)d_in[9];
    const float* Wk  = (const float*)d_in[10]; const float* bk  = (const float*)d_in[11];
    const float* Wg1 = (const float*)d_in[12]; const float* bg1 = (const float*)d_in[13];
    const float* Wg2 = (const float*)d_in[14]; const float* bg2 = (const float*)d_in[15];
    const float* Wv1 = (const float*)d_in[16]; const float* bv1 = (const float*)d_in[17];
    const float* Wv2 = (const float*)d_in[18]; const float* bv2 = (const float*)d_in[19];
    const float* Wre = (const float*)d_in[20]; const float* bre = (const float*)d_in[21];
    const float* Wra = (const float*)d_in[22]; const float* bra = (const float*)d_in[23];

    float* out   = (float*)d_out;
    float* out_s = out;
    float* out_v = out + (size_t)N_NODES * CDIM;
    float* out_r = out_v + (size_t)N_NODES * 3 * CDIM;

    float *p_sln, *p_q, *p_k, *p_h1, *p_h2, *p_x3, *p_val, *p_rattn, *p_rproj, *p_rijc, *p_wc;
    cudaGetSymbolAddress((void**)&p_sln,   g_sln);
    cudaGetSymbolAddress((void**)&p_q,     g_q);
    cudaGetSymbolAddress((void**)&p_k,     g_k);
    cudaGetSymbolAddress((void**)&p_h1,    g_h1);
    cudaGetSymbolAddress((void**)&p_h2,    g_h2);
    cudaGetSymbolAddress((void**)&p_x3,    g_x3);
    cudaGetSymbolAddress((void**)&p_val,   g_val);
    cudaGetSymbolAddress((void**)&p_rattn, g_rattn);
    cudaGetSymbolAddress((void**)&p_rproj, g_rproj);
    cudaGetSymbolAddress((void**)&p_rijc,  g_rijc);
    cudaGetSymbolAddress((void**)&p_wc,    g_wc);

    cudaFuncSetAttribute(gemm_pipe, cudaFuncAttributeMaxDynamicSharedMemorySize, SMEM_BYTES);

    cudaMemcpyAsync(out_v, v, sizeof(float) * (size_t)N_NODES * 3 * CDIM,
                    cudaMemcpyDeviceToDevice, 0);

    WSrc ws;
    ws.p[0] = Wq;  ws.p[1] = Wk;  ws.p[2] = Wg1; ws.p[3] = Wv1;
    ws.p[4] = Wg2; ws.p[5] = Wv2; ws.p[6] = Wre; ws.p[7] = Wra;
    conv_w_kernel<<<dim3(192, 8), 256>>>(ws);
    conv_rij_kernel<<<((size_t)N_EDGES * CDIM / 4 + 255) / 256, 256>>>(rij, out_r);

    init_kernel<<<(N_NODES * HEADS + 255) / 256, 256>>>();
    ln_kernel<<<N_NODES, 128>>>(s, lng, lnb, out_s);

    const int mb_n = (N_NODES + 127) / 128;   // 157
    const int mb_e = N_EDGES / 128;           // 2500

    // combined: 4 node C->C GEMMs + 3 Wra tiles + Wre, one launch (10628 blocks)
    Task8 tA;
    tA.t[0] = { p_sln,  p_wc + WQ_OFF,  bq,  p_q,     N_NODES, 128, 0, 0,   0, 0 };
    tA.t[1] = { p_sln,  p_wc + WK_OFF,  bk,  p_k,     N_NODES, 128, 0, 0,   0, mb_n };
    tA.t[2] = { p_sln,  p_wc + WG1_OFF, bg1, p_h1,    N_NODES, 128, 1, 0,   1, 2 * mb_n };
    tA.t[3] = { p_sln,  p_wc + WV1_OFF, bv1, p_h2,    N_NODES, 128, 1, 0,   1, 3 * mb_n };
    tA.t[4] = { p_rijc, p_wc + WRA_OFF, bra, p_rproj, N_EDGES, 384, 0, 0,   0, 4 * mb_n };
    tA.t[5] = { p_rijc, p_wc + WRA_OFF, bra, p_rproj, N_EDGES, 384, 0, 128, 0, 4 * mb_n + mb_e };
    tA.t[6] = { p_rijc, p_wc + WRA_OFF, bra, p_rproj, N_EDGES, 384, 0, 256, 0, 4 * mb_n + 2 * mb_e };
    tA.t[7] = { p_rijc, p_wc + WRE_OFF, bre, p_rattn, N_EDGES, 128, 1, 0,   0, 4 * mb_n + 3 * mb_e };
    gemm_pipe<<<4 * mb_n + 4 * mb_e, 256, SMEM_BYTES>>>(tA);

    // second stage: 2 node C->3C GEMMs x 3 column tiles (depends on h1,h2)
    Task8 tB;
    tB.t[0] = { p_h1, p_wc + WG2_OFF, bg2, p_x3,  N_NODES, 384, 0, 0,   0, 0 };
    tB.t[1] = { p_h1, p_wc + WG2_OFF, bg2, p_x3,  N_NODES, 384, 0, 128, 0, mb_n };
    tB.t[2] = { p_h1, p_wc + WG2_OFF, bg2, p_x3,  N_NODES, 384, 0, 256, 0, 2 * mb_n };
    tB.t[3] = { p_h2, p_wc + WV2_OFF, bv2, p_val, N_NODES, 384, 0, 0,   0, 3 * mb_n };
    tB.t[4] = { p_h2, p_wc + WV2_OFF, bv2, p_val, N_NODES, 384, 0, 128, 0, 4 * mb_n };
    tB.t[5] = { p_h2, p_wc + WV2_OFF, bv2, p_val, N_NODES, 384, 0, 256, 0, 5 * mb_n };
    tB.t[6] = tB.t[5]; tB.t[6].blk0 = 0x7FFFFFFF;
    tB.t[7] = tB.t[5]; tB.t[7].blk0 = 0x7FFFFFFF;
    gemm_pipe<<<6 * mb_n, 256, SMEM_BYTES>>>(tB);

    alpha_kernel<<<N_EDGES / 8, 256>>>(ei);
    exp_kernel<<<(N_EDGES * HEADS + 255) / 256, 256>>>(ei);
    msg_kernel<<<N_EDGES, 128>>>(ei, dir, dij, v, out_s, out_v);
}